// round 4
// baseline (speedup 1.0000x reference)
#include <cuda_runtime.h>
#include <cuda_bf16.h>
#include <math_constants.h>

#define C_DIM 128
#define D_DEG 64
#define NODE_NUM 8192
#define NEG_SLOPE 0.2f
#define NWARPS 16          // 512 threads
#define GRID_CTAS 148      // persistent: 1 CTA per SM

// Folded weights: v = W_max @ W_score[:128]; c0 = dot(b_max, W_score[:128]) + b_score
__device__ float g_v[C_DIM];
__device__ float g_c0;

__global__ void precompute_kernel(const float* __restrict__ Wmax,
                                  const float* __restrict__ bmax,
                                  const float* __restrict__ Wscore,
                                  const float* __restrict__ bscore) {
    __shared__ float ws1[C_DIM];
    int t = threadIdx.x;  // 128 threads
    ws1[t] = Wscore[t];
    __syncthreads();
    const float* row = Wmax + t * C_DIM;
    float acc = 0.f;
#pragma unroll 8
    for (int k = 0; k < C_DIM; k++) acc += row[k] * ws1[k];
    g_v[t] = acc;
    if (t == 0) {
        float c0 = bscore[0];
        for (int k = 0; k < C_DIM; k++) c0 += bmax[k] * ws1[k];
        g_c0 = c0;
    }
}

__global__ __launch_bounds__(512)
void community_kernel(const float* __restrict__ feat,
                      const float* __restrict__ mem,
                      const float* __restrict__ Wscore,
                      const float* __restrict__ Wfit,
                      const float* __restrict__ bfit,
                      float* __restrict__ out_cluster,   // [NODE_NUM, C]
                      float* __restrict__ out_scores,    // [NODE_NUM, D]
                      float* __restrict__ out_fit,       // [NODE_NUM]
                      const int* __restrict__ neighbors)
{
    __shared__ float part[NWARPS][C_DIM];   // 8KB cross-warp partials
    __shared__ float sraw[D_DEG];
    __shared__ float sarr[D_DEG];
    __shared__ float wred[NWARPS];
    __shared__ float s_const_sh;

    const int t    = threadIdx.x;
    const int lane = t & 31;
    const int wid  = t >> 5;   // 0..15

    // loop-invariant weights (registers)
    const float4 w2v   = *reinterpret_cast<const float4*>(Wscore + C_DIM + 4 * lane);
    const float  gv    = (t < C_DIM) ? g_v[t]  : 0.f;
    const float  wfitv = (t < C_DIM) ? Wfit[t] : 0.f;
    const float  bfitv = bfit[0];
    const float  c0    = g_c0;

    int node = blockIdx.x;

    // ---- prologue: ids + gathers for the first node ----
    int nid[4];
#pragma unroll
    for (int i = 0; i < 4; i++) nid[i] = neighbors[node * D_DEG + i * NWARPS + wid];
    float4 af[4], am[4];
#pragma unroll
    for (int i = 0; i < 4; i++)
        af[i] = reinterpret_cast<const float4*>(feat + (long long)nid[i] * C_DIM)[lane];
#pragma unroll
    for (int i = 0; i < 4; i++)
        am[i] = reinterpret_cast<const float4*>(mem + (long long)nid[i] * C_DIM)[lane];

    while (true) {
        const int  next     = node + GRID_CTAS;
        const bool has_next = (next < NODE_NUM);

        // ---- fold gathered rows into nbr registers ----
        float4 nb[4];
#pragma unroll
        for (int i = 0; i < 4; i++) {
            nb[i].x = af[i].x + am[i].x; nb[i].y = af[i].y + am[i].y;
            nb[i].z = af[i].z + am[i].z; nb[i].w = af[i].w + am[i].w;
        }

        // ---- start next node's id loads ASAP ----
        int nid2[4];
        if (has_next) {
#pragma unroll
            for (int i = 0; i < 4; i++)
                nid2[i] = neighbors[next * D_DEG + i * NWARPS + wid];
        }

        // ---- fused column-max + per-row score dot ----
        float4 cmax = make_float4(-CUDART_INF_F, -CUDART_INF_F, -CUDART_INF_F, -CUDART_INF_F);
#pragma unroll
        for (int i = 0; i < 4; i++) {
            cmax.x = fmaxf(cmax.x, nb[i].x);
            cmax.y = fmaxf(cmax.y, nb[i].y);
            cmax.z = fmaxf(cmax.z, nb[i].z);
            cmax.w = fmaxf(cmax.w, nb[i].w);
            float p = nb[i].x * w2v.x + nb[i].y * w2v.y + nb[i].z * w2v.z + nb[i].w * w2v.w;
#pragma unroll
            for (int o = 16; o > 0; o >>= 1) p += __shfl_xor_sync(0xffffffffu, p, o);
            if (lane == 0) sraw[i * NWARPS + wid] = p;
        }
        reinterpret_cast<float4*>(&part[wid][0])[lane] = cmax;

        // ---- issue next node's gathers BEFORE the epilogue (overlap) ----
        if (has_next) {
#pragma unroll
            for (int i = 0; i < 4; i++)
                af[i] = reinterpret_cast<const float4*>(feat + (long long)nid2[i] * C_DIM)[lane];
#pragma unroll
            for (int i = 0; i < 4; i++)
                am[i] = reinterpret_cast<const float4*>(mem + (long long)nid2[i] * C_DIM)[lane];
        }

        __syncthreads();  // B1: part + sraw ready

        // ---- s_const = dot(colmax, v) + c0 ----
        if (t < C_DIM) {
            float cm = -CUDART_INF_F;
#pragma unroll
            for (int w = 0; w < NWARPS; w++) cm = fmaxf(cm, part[w][t]);
            float p = cm * gv;
#pragma unroll
            for (int o = 16; o > 0; o >>= 1) p += __shfl_xor_sync(0xffffffffu, p, o);
            if (lane == 0) wred[wid] = p;
        }
        __syncthreads();  // B2: wred ready, part free

        // ---- warp 0: s_const + leaky-relu + segment softmax ----
        if (wid == 0) {
            const float s_const = wred[0] + wred[1] + wred[2] + wred[3] + c0;
            float a0 = s_const + sraw[lane];
            float a1 = s_const + sraw[lane + 32];
            a0 = (a0 >= 0.f) ? a0 : NEG_SLOPE * a0;
            a1 = (a1 >= 0.f) ? a1 : NEG_SLOPE * a1;
            float mx = fmaxf(a0, a1);
#pragma unroll
            for (int o = 16; o > 0; o >>= 1) mx = fmaxf(mx, __shfl_xor_sync(0xffffffffu, mx, o));
            float e0 = __expf(a0 - mx), e1 = __expf(a1 - mx);
            float sm = e0 + e1;
#pragma unroll
            for (int o = 16; o > 0; o >>= 1) sm += __shfl_xor_sync(0xffffffffu, sm, o);
            float inv = 1.f / sm;
            sarr[lane]      = e0 * inv;
            sarr[lane + 32] = e1 * inv;
        }
        __syncthreads();  // B3: sarr ready

        if (t < D_DEG) out_scores[node * D_DEG + t] = sarr[t];

        // ---- weighted pooling from registers ----
        float4 pool = make_float4(0.f, 0.f, 0.f, 0.f);
#pragma unroll
        for (int i = 0; i < 4; i++) {
            float sc = sarr[i * NWARPS + wid];
            pool.x = fmaf(sc, nb[i].x, pool.x);
            pool.y = fmaf(sc, nb[i].y, pool.y);
            pool.z = fmaf(sc, nb[i].z, pool.z);
            pool.w = fmaf(sc, nb[i].w, pool.w);
        }
        reinterpret_cast<float4*>(&part[wid][0])[lane] = pool;
        __syncthreads();  // B4: pool partials ready

        // ---- cross-warp sum, write cluster, fused fitness dot ----
        if (t < C_DIM) {
            float cf = 0.f;
#pragma unroll
            for (int w = 0; w < NWARPS; w++) cf += part[w][t];
            out_cluster[node * C_DIM + t] = cf;
            float p = cf * wfitv;
#pragma unroll
            for (int o = 16; o > 0; o >>= 1) p += __shfl_xor_sync(0xffffffffu, p, o);
            if (lane == 0) wred[wid] = p;
        }
        __syncthreads();  // B5: wred ready; part free for next iter

        if (t == 0) {
            float s = wred[0] + wred[1] + wred[2] + wred[3] + bfitv;
            out_fit[node] = 1.f / (1.f + __expf(-s));
        }
        // wred is next written after B1 of the next iteration -> no race with t==0 read.

        if (!has_next) break;
        node = next;
    }
}

extern "C" void kernel_launch(void* const* d_in, const int* in_sizes, int n_in,
                              void* d_out, int out_size) {
    const float* feat   = (const float*)d_in[0];
    const float* mem    = (const float*)d_in[1];
    const float* Wmax   = (const float*)d_in[2];
    const float* bmax   = (const float*)d_in[3];
    const float* Wscore = (const float*)d_in[4];
    const float* bscore = (const float*)d_in[5];
    const float* Wfit   = (const float*)d_in[6];
    const float* bfit   = (const float*)d_in[7];
    const int*   nbrs   = (const int*)d_in[8];

    float* out = (float*)d_out;
    float* out_cluster = out;                                        // 8192*128
    float* out_scores  = out + NODE_NUM * C_DIM;                     // 8192*64
    float* out_fit     = out + NODE_NUM * C_DIM + NODE_NUM * D_DEG;  // 8192

    precompute_kernel<<<1, 128>>>(Wmax, bmax, Wscore, bscore);
    community_kernel<<<GRID_CTAS, 512>>>(feat, mem, Wscore, Wfit, bfit,
                                         out_cluster, out_scores, out_fit, nbrs);
}

// round 6
// speedup vs baseline: 1.2904x; 1.2904x over previous
#include <cuda_runtime.h>
#include <cuda_bf16.h>
#include <math_constants.h>
#include <cstdint>

#define C_DIM 128
#define D_DEG 64
#define NODE_NUM 8192
#define NEG_SLOPE 0.2f
#define NWARPS 16            // 512 threads
#define GRID_CTAS 296        // 2 persistent CTAs per SM

// smem layout (dynamic)
#define OFF_STF   0                       // stage feat  [64][128] f32  32KB
#define OFF_STM   32768                   // stage mem   [64][128] f32  32KB
#define OFF_PART  65536                   // part [16][128] f32          8KB
#define OFF_SRAW  73728                   // [64] f32
#define OFF_SARR  73984                   // [64] f32
#define OFF_WRED  74240                   // [16] f32
#define SMEM_BYTES 74304

// Folded weights: v = W_max @ W_score[:128]; c0 = dot(b_max, W_score[:128]) + b_score
__device__ float g_v[C_DIM];
__device__ float g_c0;

__global__ void precompute_kernel(const float* __restrict__ Wmax,
                                  const float* __restrict__ bmax,
                                  const float* __restrict__ Wscore,
                                  const float* __restrict__ bscore) {
    __shared__ float ws1[C_DIM];
    int t = threadIdx.x;  // 128 threads
    ws1[t] = Wscore[t];
    __syncthreads();
    const float* row = Wmax + t * C_DIM;
    float acc = 0.f;
#pragma unroll 8
    for (int k = 0; k < C_DIM; k++) acc += row[k] * ws1[k];
    g_v[t] = acc;
    if (t == 0) {
        float c0 = bscore[0];
        for (int k = 0; k < C_DIM; k++) c0 += bmax[k] * ws1[k];
        g_c0 = c0;
    }
}

__device__ __forceinline__ void cp16(unsigned int dst, const void* src) {
    asm volatile("cp.async.cg.shared.global [%0], [%1], 16;\n"
                 :: "r"(dst), "l"(src) : "memory");
}

__global__ __launch_bounds__(512, 2)
void community_kernel(const float* __restrict__ feat,
                      const float* __restrict__ mem,
                      const float* __restrict__ Wscore,
                      const float* __restrict__ Wfit,
                      const float* __restrict__ bfit,
                      float* __restrict__ out_cluster,   // [NODE_NUM, C]
                      float* __restrict__ out_scores,    // [NODE_NUM, D]
                      float* __restrict__ out_fit,       // [NODE_NUM]
                      const int* __restrict__ neighbors)
{
    extern __shared__ char smem[];
    float* stf  = (float*)(smem + OFF_STF);    // [64][128]
    float* stm  = (float*)(smem + OFF_STM);    // [64][128]
    float* part = (float*)(smem + OFF_PART);   // [16][128]
    float* sraw = (float*)(smem + OFF_SRAW);
    float* sarr = (float*)(smem + OFF_SARR);
    float* wred = (float*)(smem + OFF_WRED);

    const unsigned int stf_u = (unsigned int)__cvta_generic_to_shared(stf);
    const unsigned int stm_u = (unsigned int)__cvta_generic_to_shared(stm);

    const int t    = threadIdx.x;
    const int lane = t & 31;
    const int wid  = t >> 5;   // 0..15

    // loop-invariant weights in registers
    const float4 w2v   = *reinterpret_cast<const float4*>(Wscore + C_DIM + 4 * lane);
    const float  gv    = (t < C_DIM) ? g_v[t]  : 0.f;
    const float  wfitv = (t < C_DIM) ? Wfit[t] : 0.f;
    const float  bfitv = bfit[0];
    const float  c0    = g_c0;

    int node = blockIdx.x;

    // ---- prologue: issue cp.async gathers for first node ----
    {
#pragma unroll
        for (int i = 0; i < 4; i++) {
            int row = i * NWARPS + wid;
            long long nid = neighbors[node * D_DEG + row];
            cp16(stf_u + (unsigned)(row * C_DIM + lane * 4) * 4u, feat + nid * C_DIM + lane * 4);
            cp16(stm_u + (unsigned)(row * C_DIM + lane * 4) * 4u, mem  + nid * C_DIM + lane * 4);
        }
        asm volatile("cp.async.commit_group;\n" ::: "memory");
    }

    while (true) {
        const int  next     = node + GRID_CTAS;
        const bool has_next = (next < NODE_NUM);

        // ---- wait for this node's stage (own bytes only -> no barrier) ----
        asm volatile("cp.async.wait_group 0;\n" ::: "memory");

        // ---- sum stage -> registers (each lane reads its own fetched bytes) ----
        float4 nb[4];
#pragma unroll
        for (int i = 0; i < 4; i++) {
            int row = i * NWARPS + wid;
            float4 a = *reinterpret_cast<const float4*>(stf + row * C_DIM + lane * 4);
            float4 b = *reinterpret_cast<const float4*>(stm + row * C_DIM + lane * 4);
            nb[i].x = a.x + b.x; nb[i].y = a.y + b.y;
            nb[i].z = a.z + b.z; nb[i].w = a.w + b.w;
        }

        // ---- immediately issue next node's gathers into the (now free) stage ----
        if (has_next) {
#pragma unroll
            for (int i = 0; i < 4; i++) {
                int row = i * NWARPS + wid;
                long long nid = neighbors[next * D_DEG + row];
                cp16(stf_u + (unsigned)(row * C_DIM + lane * 4) * 4u, feat + nid * C_DIM + lane * 4);
                cp16(stm_u + (unsigned)(row * C_DIM + lane * 4) * 4u, mem  + nid * C_DIM + lane * 4);
            }
            asm volatile("cp.async.commit_group;\n" ::: "memory");
        }

        // ---- fused column-max + per-row score dot ----
        float4 cmax = make_float4(-CUDART_INF_F, -CUDART_INF_F, -CUDART_INF_F, -CUDART_INF_F);
#pragma unroll
        for (int i = 0; i < 4; i++) {
            cmax.x = fmaxf(cmax.x, nb[i].x);
            cmax.y = fmaxf(cmax.y, nb[i].y);
            cmax.z = fmaxf(cmax.z, nb[i].z);
            cmax.w = fmaxf(cmax.w, nb[i].w);
            float p = nb[i].x * w2v.x + nb[i].y * w2v.y + nb[i].z * w2v.z + nb[i].w * w2v.w;
#pragma unroll
            for (int o = 16; o > 0; o >>= 1) p += __shfl_xor_sync(0xffffffffu, p, o);
            if (lane == 0) sraw[i * NWARPS + wid] = p;
        }
        reinterpret_cast<float4*>(part + wid * C_DIM)[lane] = cmax;
        __syncthreads();  // B1: part + sraw ready

        // ---- s_const = dot(colmax, v) + c0 ----
        if (t < C_DIM) {
            float cm = -CUDART_INF_F;
#pragma unroll
            for (int w = 0; w < NWARPS; w++) cm = fmaxf(cm, part[w * C_DIM + t]);
            float p = cm * gv;
#pragma unroll
            for (int o = 16; o > 0; o >>= 1) p += __shfl_xor_sync(0xffffffffu, p, o);
            if (lane == 0) wred[wid] = p;
        }
        __syncthreads();  // B2

        // ---- warp 0: leaky-relu + segment softmax ----
        if (wid == 0) {
            const float s_const = wred[0] + wred[1] + wred[2] + wred[3] + c0;
            float a0 = s_const + sraw[lane];
            float a1 = s_const + sraw[lane + 32];
            a0 = (a0 >= 0.f) ? a0 : NEG_SLOPE * a0;
            a1 = (a1 >= 0.f) ? a1 : NEG_SLOPE * a1;
            float mx = fmaxf(a0, a1);
#pragma unroll
            for (int o = 16; o > 0; o >>= 1) mx = fmaxf(mx, __shfl_xor_sync(0xffffffffu, mx, o));
            float e0 = __expf(a0 - mx), e1 = __expf(a1 - mx);
            float sm = e0 + e1;
#pragma unroll
            for (int o = 16; o > 0; o >>= 1) sm += __shfl_xor_sync(0xffffffffu, sm, o);
            float inv = 1.f / sm;
            sarr[lane]      = e0 * inv;
            sarr[lane + 32] = e1 * inv;
        }
        __syncthreads();  // B3: sarr ready

        if (t < D_DEG) out_scores[node * D_DEG + t] = sarr[t];

        // ---- weighted pooling from registers ----
        float4 pool = make_float4(0.f, 0.f, 0.f, 0.f);
#pragma unroll
        for (int i = 0; i < 4; i++) {
            float sc = sarr[i * NWARPS + wid];
            pool.x = fmaf(sc, nb[i].x, pool.x);
            pool.y = fmaf(sc, nb[i].y, pool.y);
            pool.z = fmaf(sc, nb[i].z, pool.z);
            pool.w = fmaf(sc, nb[i].w, pool.w);
        }
        reinterpret_cast<float4*>(part + wid * C_DIM)[lane] = pool;
        __syncthreads();  // B4

        // ---- cross-warp sum, write cluster, fused fitness dot ----
        if (t < C_DIM) {
            float cf = 0.f;
#pragma unroll
            for (int w = 0; w < NWARPS; w++) cf += part[w * C_DIM + t];
            out_cluster[node * C_DIM + t] = cf;
            float p = cf * wfitv;
#pragma unroll
            for (int o = 16; o > 0; o >>= 1) p += __shfl_xor_sync(0xffffffffu, p, o);
            if (lane == 0) wred[wid] = p;
        }
        __syncthreads();  // B5

        if (t == 0) {
            float s = wred[0] + wred[1] + wred[2] + wred[3] + bfitv;
            out_fit[node] = 1.f / (1.f + __expf(-s));
        }
        // wred next written after B1 of next iter; t0 must pass B1 itself -> safe.

        if (!has_next) break;
        node = next;
    }
}

extern "C" void kernel_launch(void* const* d_in, const int* in_sizes, int n_in,
                              void* d_out, int out_size) {
    const float* feat   = (const float*)d_in[0];
    const float* mem    = (const float*)d_in[1];
    const float* Wmax   = (const float*)d_in[2];
    const float* bmax   = (const float*)d_in[3];
    const float* Wscore = (const float*)d_in[4];
    const float* bscore = (const float*)d_in[5];
    const float* Wfit   = (const float*)d_in[6];
    const float* bfit   = (const float*)d_in[7];
    const int*   nbrs   = (const int*)d_in[8];

    float* out = (float*)d_out;
    float* out_cluster = out;                                        // 8192*128
    float* out_scores  = out + NODE_NUM * C_DIM;                     // 8192*64
    float* out_fit     = out + NODE_NUM * C_DIM + NODE_NUM * D_DEG;  // 8192

    cudaFuncSetAttribute(community_kernel,
                         cudaFuncAttributeMaxDynamicSharedMemorySize, SMEM_BYTES);

    precompute_kernel<<<1, 128>>>(Wmax, bmax, Wscore, bscore);
    community_kernel<<<GRID_CTAS, 512, SMEM_BYTES>>>(feat, mem, Wscore, Wfit, bfit,
                                                     out_cluster, out_scores, out_fit, nbrs);
}